// round 6
// baseline (speedup 1.0000x reference)
#include <cuda_runtime.h>

// Problem constants
#define CN0 2048
#define CN1 8192
#define CN2 4096

// ---------------------------------------------------------------------------
// Scratch (device globals — no allocation allowed)
// ---------------------------------------------------------------------------
__device__ float g_X0cat[CN0 * 256];   // [x0 | x0p]
__device__ float g_T10[CN0 * 256];     // l0 @ X0cat
__device__ float g_T20[CN0 * 256];     // 2 l0 T10 - X0cat
__device__ float g_X1cat[CN1 * 256];   // [x1 | x1p]
__device__ float g_T1l[CN1 * 128];     // l1l @ x1
__device__ float g_T2l[CN1 * 128];
__device__ float g_T1u[CN1 * 256];     // l1u @ X1cat
__device__ float g_T2u[CN1 * 256];
__device__ float g_X2cat[CN2 * 256];   // [x2n | x2]
__device__ float g_T12[CN2 * 256];     // l2 @ X2cat
__device__ float g_T22[CN2 * 256];
__device__ float g_W0[6 * 16384];      // repacked w0: [c][i][o]
__device__ float g_W1[8 * 16384];
__device__ float g_W2[6 * 16384];

// ---------------------------------------------------------------------------
// Packed f32x2 helpers (Blackwell FFMA2 path)
// ---------------------------------------------------------------------------
__device__ __forceinline__ unsigned long long dup2(float a) {
    unsigned long long r;
    unsigned u = __float_as_uint(a);
    asm("mov.b64 %0, {%1, %1};" : "=l"(r) : "r"(u));
    return r;
}
__device__ __forceinline__ void fma2(unsigned long long& d,
                                     unsigned long long a,
                                     unsigned long long b) {
    asm("fma.rn.f32x2 %0, %1, %2, %0;" : "+l"(d) : "l"(a), "l"(b));
}
__device__ __forceinline__ float2 un2(unsigned long long v) {
    unsigned lo, hi;
    asm("mov.b64 {%0, %1}, %2;" : "=r"(lo), "=r"(hi) : "l"(v));
    return make_float2(__uint_as_float(lo), __uint_as_float(hi));
}

// ---------------------------------------------------------------------------
// Tile loaders (128-wide M/N tile, 16-deep K tile, 256 threads)
// ---------------------------------------------------------------------------
__device__ __forceinline__ void ldA_n(float (*As)[132], const float* __restrict__ A,
                                      int lda, int m0, int k0, int tid) {
#pragma unroll
    for (int l = 0; l < 2; l++) {
        int idx = tid + l * 256;
        int row = idx >> 2;              // 0..127
        int kq  = (idx & 3) << 2;        // 0,4,8,12
        float4 v = *(const float4*)(A + (size_t)(m0 + row) * lda + k0 + kq);
        As[kq + 0][row] = v.x;
        As[kq + 1][row] = v.y;
        As[kq + 2][row] = v.z;
        As[kq + 3][row] = v.w;
    }
}
__device__ __forceinline__ void ldA_t(float (*As)[132], const float* __restrict__ A,
                                      int lda, int m0, int k0, int tid) {
#pragma unroll
    for (int l = 0; l < 2; l++) {
        int idx = tid + l * 256;
        int kr = idx >> 5;               // 0..15
        int mq = (idx & 31) << 2;        // 0..124
        *(float4*)(&As[kr][mq]) =
            *(const float4*)(A + (size_t)(k0 + kr) * lda + m0 + mq);
    }
}
__device__ __forceinline__ void ldB(float (*Bs)[128], const float* __restrict__ B,
                                    int ldb, int n0, int k0,
                                    const float* __restrict__ bscale, int bss, int tid) {
#pragma unroll
    for (int l = 0; l < 2; l++) {
        int idx = tid + l * 256;
        int kr = idx >> 5;
        int nq = (idx & 31) << 2;
        float4 v = *(const float4*)(B + (size_t)(k0 + kr) * ldb + n0 + nq);
        if (bscale) {
            float s = bscale[(size_t)(k0 + kr) * bss];
            v.x *= s; v.y *= s; v.z *= s; v.w *= s;
        }
        *(float4*)(&Bs[kr][nq]) = v;
    }
}

// Inner product over one 16-deep K tile. acc[i][j] holds column pairs:
//   j=0: cols tx*4+{0,1}; j=1: tx*4+{2,3}; j=2: 64+tx*4+{0,1}; j=3: 64+tx*4+{2,3}
// rows: m0 + ty*8 + i.
__device__ __forceinline__ void mm_inner(float (*As)[132], float (*Bs)[128],
                                         int tx, int ty,
                                         unsigned long long acc[8][4]) {
#pragma unroll
    for (int kk = 0; kk < 16; kk++) {
        float4 a0 = *(const float4*)(&As[kk][ty * 8]);
        float4 a1 = *(const float4*)(&As[kk][ty * 8 + 4]);
        double2 bA = *(const double2*)(&Bs[kk][tx * 4]);
        double2 bB = *(const double2*)(&Bs[kk][64 + tx * 4]);
        unsigned long long bp[4];
        bp[0] = __double_as_longlong(bA.x);
        bp[1] = __double_as_longlong(bA.y);
        bp[2] = __double_as_longlong(bB.x);
        bp[3] = __double_as_longlong(bB.y);
        float av[8] = {a0.x, a0.y, a0.z, a0.w, a1.x, a1.y, a1.z, a1.w};
#pragma unroll
        for (int i = 0; i < 8; i++) {
            unsigned long long ap = dup2(av[i]);
#pragma unroll
            for (int j = 0; j < 4; j++) fma2(acc[i][j], ap, bp[j]);
        }
    }
}

// ---------------------------------------------------------------------------
// Batched GEMM: several independent GEMMs in one launch (fills the chip)
// ---------------------------------------------------------------------------
struct GemmDesc {
    const float* A;
    const float* B;
    const float* S;       // subtrahend for Chebyshev epilogue (epi=1)
    const float* bscale;  // diag matrix base for B row scaling (or null)
    const float* crow;    // diag matrix base for C row scaling (or null)
    float* C;
    int lda, ldb, lds, ldc;
    int bss, crs;         // diag strides (N+1)
    int K, mtiles, ntiles, tile_base;
    int transa, epi;      // epi: 0 = store (opt. row-scaled), 1 = 2*AB - S
};
struct BatchArgs { GemmDesc d[4]; int nd; };

__global__ __launch_bounds__(256, 2) void gemm_batched(BatchArgs args) {
    __shared__ __align__(16) float As[16][132];
    __shared__ __align__(16) float Bs[16][128];
    int tid = threadIdx.x;
    int tx = tid & 15, ty = tid >> 4;
    int bid = blockIdx.x;

    int di = 0;
#pragma unroll
    for (int i = 1; i < 4; i++)
        if (i < args.nd && bid >= args.d[i].tile_base) di = i;
    const GemmDesc& g = args.d[di];

    int tile = bid - g.tile_base;
    int bm = tile / g.ntiles;
    int bn = tile - bm * g.ntiles;
    int m0 = bm << 7, n0 = bn << 7;

    unsigned long long acc[8][4];
#pragma unroll
    for (int i = 0; i < 8; i++)
#pragma unroll
        for (int j = 0; j < 4; j++) acc[i][j] = 0ull;

    const float* A = g.A;
    const float* B = g.B;
    const float* bscale = g.bscale;
    int lda = g.lda, ldb = g.ldb, K = g.K, transa = g.transa, bss = g.bss;

#pragma unroll 1
    for (int k0 = 0; k0 < K; k0 += 16) {
        if (transa) ldA_t(As, A, lda, m0, k0, tid);
        else        ldA_n(As, A, lda, m0, k0, tid);
        ldB(Bs, B, ldb, n0, k0, bscale, bss, tid);
        __syncthreads();
        mm_inner(As, Bs, tx, ty, acc);
        __syncthreads();
    }

    float* C = g.C;
    int ldc = g.ldc;
    if (g.epi == 0) {
        const float* crow = g.crow;
        int crs = g.crs;
#pragma unroll
        for (int i = 0; i < 8; i++) {
            int mr = m0 + ty * 8 + i;
            float s = crow ? crow[(size_t)mr * crs] : 1.0f;
#pragma unroll
            for (int gi = 0; gi < 2; gi++) {
                float2 lo = un2(acc[i][2 * gi]);
                float2 hi = un2(acc[i][2 * gi + 1]);
                float4 v = make_float4(lo.x * s, lo.y * s, hi.x * s, hi.y * s);
                *(float4*)(C + (size_t)mr * ldc + n0 + gi * 64 + tx * 4) = v;
            }
        }
    } else {
        const float* S = g.S;
        int lds = g.lds;
#pragma unroll
        for (int i = 0; i < 8; i++) {
            int mr = m0 + ty * 8 + i;
#pragma unroll
            for (int gi = 0; gi < 2; gi++) {
                int col = n0 + gi * 64 + tx * 4;
                float4 sv = *(const float4*)(S + (size_t)mr * lds + col);
                float2 lo = un2(acc[i][2 * gi]);
                float2 hi = un2(acc[i][2 * gi + 1]);
                float4 v = make_float4(2.0f * lo.x - sv.x, 2.0f * lo.y - sv.y,
                                       2.0f * hi.x - sv.z, 2.0f * hi.y - sv.w);
                *(float4*)(C + (size_t)mr * ldc + col) = v;
            }
        }
    }
}

// ---------------------------------------------------------------------------
// Combine: y = relu(sum_c A_c @ W_c), one CTA per 128-row tile, loops channels
// ---------------------------------------------------------------------------
__global__ __launch_bounds__(256, 2) void combine_kernel(float* __restrict__ out) {
    __shared__ __align__(16) float As[16][132];
    __shared__ __align__(16) float Bs[16][128];
    int tid = threadIdx.x;
    int tx = tid & 15, ty = tid >> 4;
    int bid = blockIdx.x;

    const float* chp[8];
    int chl[8];
    const float* W;
    float* op;
    int nc, bm;
    if (bid < 16) {                 // order 0: rows 2048
        bm = bid; nc = 6; W = g_W0; op = out;
        chp[0] = g_X0cat;        chl[0] = 256;
        chp[1] = g_T10;          chl[1] = 256;
        chp[2] = g_T20;          chl[2] = 256;
        chp[3] = g_X0cat + 128;  chl[3] = 256;
        chp[4] = g_T10 + 128;    chl[4] = 256;
        chp[5] = g_T20 + 128;    chl[5] = 256;
    } else if (bid < 80) {          // order 1: rows 8192
        bm = bid - 16; nc = 8; W = g_W1; op = out + (size_t)CN0 * 128;
        chp[0] = g_X1cat;        chl[0] = 256;
        chp[1] = g_T1l;          chl[1] = 128;
        chp[2] = g_T2l;          chl[2] = 128;
        chp[3] = g_T1u;          chl[3] = 256;
        chp[4] = g_T2u;          chl[4] = 256;
        chp[5] = g_X1cat + 128;  chl[5] = 256;
        chp[6] = g_T1u + 128;    chl[6] = 256;
        chp[7] = g_T2u + 128;    chl[7] = 256;
    } else {                        // order 2: rows 4096
        bm = bid - 80; nc = 6; W = g_W2; op = out + (size_t)(CN0 + CN1) * 128;
        chp[0] = g_X2cat;        chl[0] = 256;
        chp[1] = g_T12;          chl[1] = 256;
        chp[2] = g_T22;          chl[2] = 256;
        chp[3] = g_X2cat + 128;  chl[3] = 256;
        chp[4] = g_T12 + 128;    chl[4] = 256;
        chp[5] = g_T22 + 128;    chl[5] = 256;
    }
    int m0 = bm << 7;

    unsigned long long acc[8][4];
#pragma unroll
    for (int i = 0; i < 8; i++)
#pragma unroll
        for (int j = 0; j < 4; j++) acc[i][j] = 0ull;

#pragma unroll 1
    for (int c = 0; c < nc; c++) {
        const float* A = chp[c];
        int lda = chl[c];
        const float* Bw = W + c * 16384;
#pragma unroll 1
        for (int k0 = 0; k0 < 128; k0 += 16) {
            ldA_n(As, A, lda, m0, k0, tid);
            ldB(Bs, Bw, 128, 0, k0, nullptr, 0, tid);
            __syncthreads();
            mm_inner(As, Bs, tx, ty, acc);
            __syncthreads();
        }
    }

#pragma unroll
    for (int i = 0; i < 8; i++) {
        int mr = m0 + ty * 8 + i;
#pragma unroll
        for (int gi = 0; gi < 2; gi++) {
            float2 lo = un2(acc[i][2 * gi]);
            float2 hi = un2(acc[i][2 * gi + 1]);
            float4 v = make_float4(fmaxf(lo.x, 0.0f), fmaxf(lo.y, 0.0f),
                                   fmaxf(hi.x, 0.0f), fmaxf(hi.y, 0.0f));
            *(float4*)(op + (size_t)mr * 128 + gi * 64 + tx * 4) = v;
        }
    }
}

// ---------------------------------------------------------------------------
// Prep kernels
// ---------------------------------------------------------------------------
// Repack w[i][o][c] (k innermost) -> W[c][i][o]
__global__ void pack_kernel(float* __restrict__ dst, const float* __restrict__ w, int nk) {
    int idx = blockIdx.x * 256 + threadIdx.x;   // over 128*128 (i,o) pairs
    if (idx < 16384) {
        for (int c = 0; c < nk; c++) dst[c * 16384 + idx] = w[idx * nk + c];
    }
}
// Copy [rows,128] (ld 128) -> dst (ld 256)
__global__ void copy_kernel(float* __restrict__ dst, const float* __restrict__ src, int rows) {
    int idx = blockIdx.x * 256 + threadIdx.x;
    int r = idx >> 5, q = (idx & 31) << 2;
    if (r < rows)
        *(float4*)(dst + (size_t)r * 256 + q) = *(const float4*)(src + (size_t)r * 128 + q);
}

// ---------------------------------------------------------------------------
// Host launcher
// ---------------------------------------------------------------------------
static GemmDesc mk(const float* A, int lda, int ta,
                   const float* B, int ldb, const float* bs, int bss,
                   float* C, int ldc,
                   const float* cr, int crs,
                   const float* S, int lds,
                   int K, int mt, int nt, int base, int epi) {
    GemmDesc g;
    g.A = A; g.lda = lda; g.transa = ta;
    g.B = B; g.ldb = ldb; g.bscale = bs; g.bss = bss;
    g.C = C; g.ldc = ldc;
    g.crow = cr; g.crs = crs;
    g.S = S; g.lds = lds;
    g.K = K; g.mtiles = mt; g.ntiles = nt; g.tile_base = base; g.epi = epi;
    return g;
}

extern "C" void kernel_launch(void* const* d_in, const int* in_sizes, int n_in,
                              void* d_out, int out_size) {
    const float* x0  = (const float*)d_in[0];
    const float* x1  = (const float*)d_in[1];
    const float* x2  = (const float*)d_in[2];
    const float* b1  = (const float*)d_in[3];
    const float* b2  = (const float*)d_in[4];
    const float* l0  = (const float*)d_in[5];
    const float* l1l = (const float*)d_in[6];
    const float* l1u = (const float*)d_in[7];
    const float* l2  = (const float*)d_in[8];
    const float* d1  = (const float*)d_in[9];    // diag matrix [N0,N0]
    const float* d3  = (const float*)d_in[10];   // diag matrix [N2,N2]
    const float* d5  = (const float*)d_in[11];   // diag matrix [N1,N1]
    const float* w0  = (const float*)d_in[12];
    const float* w1  = (const float*)d_in[13];
    const float* w2  = (const float*)d_in[14];
    float* out = (float*)d_out;
    (void)in_sizes; (void)n_in; (void)out_size;

    float *X0cat, *T10, *T20, *X1cat, *T1l, *T2l, *T1u, *T2u, *X2cat, *T12, *T22;
    float *W0, *W1, *W2;
    cudaGetSymbolAddress((void**)&X0cat, g_X0cat);
    cudaGetSymbolAddress((void**)&T10,   g_T10);
    cudaGetSymbolAddress((void**)&T20,   g_T20);
    cudaGetSymbolAddress((void**)&X1cat, g_X1cat);
    cudaGetSymbolAddress((void**)&T1l,   g_T1l);
    cudaGetSymbolAddress((void**)&T2l,   g_T2l);
    cudaGetSymbolAddress((void**)&T1u,   g_T1u);
    cudaGetSymbolAddress((void**)&T2u,   g_T2u);
    cudaGetSymbolAddress((void**)&X2cat, g_X2cat);
    cudaGetSymbolAddress((void**)&T12,   g_T12);
    cudaGetSymbolAddress((void**)&T22,   g_T22);
    cudaGetSymbolAddress((void**)&W0,    g_W0);
    cudaGetSymbolAddress((void**)&W1,    g_W1);
    cudaGetSymbolAddress((void**)&W2,    g_W2);

    // Prep: weight repack + feature copies into concatenated panels
    pack_kernel<<<64, 256>>>(W0, w0, 6);
    pack_kernel<<<64, 256>>>(W1, w1, 8);
    pack_kernel<<<64, 256>>>(W2, w2, 6);
    copy_kernel<<<CN0 * 32 / 256, 256>>>(X0cat,       x0, CN0);  // X0cat[:, :128] = x0
    copy_kernel<<<CN1 * 32 / 256, 256>>>(X1cat,       x1, CN1);  // X1cat[:, :128] = x1
    copy_kernel<<<CN2 * 32 / 256, 256>>>(X2cat + 128, x2, CN2);  // X2cat[:,128:]  = x2

    // Wave 1: projections (all independent) — 112 CTAs
    BatchArgs ba; ba.nd = 3;
    // x0p = d1_inv * (b1 @ x1) -> X0cat[:,128:]
    ba.d[0] = mk(b1, CN1, 0, x1, 128, nullptr, 0, X0cat + 128, 256,
                 d1, CN0 + 1, nullptr, 0, CN1, 16, 1, 0, 0);
    // x1p = b2 @ (d3 * x2) -> X1cat[:,128:]
    ba.d[1] = mk(b2, CN2, 0, x2, 128, d3, CN2 + 1, X1cat + 128, 256,
                 nullptr, 0, nullptr, 0, CN2, 64, 1, 16, 0);
    // x2n = b2^T @ (d5_pinv * x1) -> X2cat[:,:128]
    ba.d[2] = mk(b2, CN2, 1, x1, 128, d5, CN1 + 1, X2cat, 256,
                 nullptr, 0, nullptr, 0, CN1, 32, 1, 80, 0);
    gemm_batched<<<112, 256>>>(ba);

    // Wave 2: first Chebyshev terms T1 = L @ X — 288 CTAs
    BatchArgs bb; bb.nd = 4;
    bb.d[0] = mk(l0,  CN0, 0, X0cat, 256, nullptr, 0, T10, 256,
                 nullptr, 0, nullptr, 0, CN0, 16, 2, 0, 0);
    bb.d[1] = mk(l1l, CN1, 0, x1,    128, nullptr, 0, T1l, 128,
                 nullptr, 0, nullptr, 0, CN1, 64, 1, 32, 0);
    bb.d[2] = mk(l1u, CN1, 0, X1cat, 256, nullptr, 0, T1u, 256,
                 nullptr, 0, nullptr, 0, CN1, 64, 2, 96, 0);
    bb.d[3] = mk(l2,  CN2, 0, X2cat, 256, nullptr, 0, T12, 256,
                 nullptr, 0, nullptr, 0, CN2, 32, 2, 224, 0);
    gemm_batched<<<288, 256>>>(bb);

    // Wave 3: second Chebyshev terms T2 = 2 L T1 - X — 288 CTAs
    BatchArgs bc; bc.nd = 4;
    bc.d[0] = mk(l0,  CN0, 0, T10, 256, nullptr, 0, T20, 256,
                 nullptr, 0, X0cat, 256, CN0, 16, 2, 0, 1);
    bc.d[1] = mk(l1l, CN1, 0, T1l, 128, nullptr, 0, T2l, 128,
                 nullptr, 0, x1, 128, CN1, 64, 1, 32, 1);
    bc.d[2] = mk(l1u, CN1, 0, T1u, 256, nullptr, 0, T2u, 256,
                 nullptr, 0, X1cat, 256, CN1, 64, 2, 96, 1);
    bc.d[3] = mk(l2,  CN2, 0, T12, 256, nullptr, 0, T22, 256,
                 nullptr, 0, X2cat, 256, CN2, 32, 2, 224, 1);
    gemm_batched<<<288, 256>>>(bc);

    // Wave 4: channel combine + relu — 112 CTAs
    combine_kernel<<<112, 256>>>(out);
}

// round 7
// speedup vs baseline: 1.0036x; 1.0036x over previous
#include <cuda_runtime.h>

// Problem constants
#define CN0 2048
#define CN1 8192
#define CN2 4096

// ---------------------------------------------------------------------------
// Scratch (device globals — no allocation allowed)
// ---------------------------------------------------------------------------
__device__ float g_X0cat[CN0 * 256];   // [x0 | x0p]
__device__ float g_T10[CN0 * 256];     // l0 @ X0cat
__device__ float g_T20[CN0 * 256];     // 2 l0 T10 - X0cat
__device__ float g_X1cat[CN1 * 256];   // [x1 | x1p]
__device__ float g_T1l[CN1 * 128];     // l1l @ x1
__device__ float g_T2l[CN1 * 128];
__device__ float g_T1u[CN1 * 256];     // l1u @ X1cat
__device__ float g_T2u[CN1 * 256];
__device__ float g_X2cat[CN2 * 256];   // [x2n | x2]
__device__ float g_T12[CN2 * 256];     // l2 @ X2cat
__device__ float g_T22[CN2 * 256];
__device__ float g_W0[6 * 16384];      // repacked w0: [c][i][o]
__device__ float g_W1[8 * 16384];
__device__ float g_W2[6 * 16384];

// ---------------------------------------------------------------------------
// Packed f32x2 helpers (Blackwell FFMA2 path)
// ---------------------------------------------------------------------------
__device__ __forceinline__ unsigned long long dup2(float a) {
    unsigned long long r;
    unsigned u = __float_as_uint(a);
    asm("mov.b64 %0, {%1, %1};" : "=l"(r) : "r"(u));
    return r;
}
__device__ __forceinline__ void fma2(unsigned long long& d,
                                     unsigned long long a,
                                     unsigned long long b) {
    asm("fma.rn.f32x2 %0, %1, %2, %0;" : "+l"(d) : "l"(a), "l"(b));
}
__device__ __forceinline__ float2 un2(unsigned long long v) {
    unsigned lo, hi;
    asm("mov.b64 {%0, %1}, %2;" : "=r"(lo), "=r"(hi) : "l"(v));
    return make_float2(__uint_as_float(lo), __uint_as_float(hi));
}

// ---------------------------------------------------------------------------
// Tile loaders (128-wide M/N tile, 16-deep K tile, 256 threads)
// ---------------------------------------------------------------------------
__device__ __forceinline__ void ldA_n(float (*As)[132], const float* __restrict__ A,
                                      int lda, int m0, int k0, int tid) {
#pragma unroll
    for (int l = 0; l < 2; l++) {
        int idx = tid + l * 256;
        int row = idx >> 2;              // 0..127
        int kq  = (idx & 3) << 2;        // 0,4,8,12
        float4 v = *(const float4*)(A + (size_t)(m0 + row) * lda + k0 + kq);
        As[kq + 0][row] = v.x;
        As[kq + 1][row] = v.y;
        As[kq + 2][row] = v.z;
        As[kq + 3][row] = v.w;
    }
}
__device__ __forceinline__ void ldA_t(float (*As)[132], const float* __restrict__ A,
                                      int lda, int m0, int k0, int tid) {
#pragma unroll
    for (int l = 0; l < 2; l++) {
        int idx = tid + l * 256;
        int kr = idx >> 5;               // 0..15
        int mq = (idx & 31) << 2;        // 0..124
        *(float4*)(&As[kr][mq]) =
            *(const float4*)(A + (size_t)(k0 + kr) * lda + m0 + mq);
    }
}
__device__ __forceinline__ void ldB(float (*Bs)[128], const float* __restrict__ B,
                                    int ldb, int n0, int k0,
                                    const float* __restrict__ bscale, int bss, int tid) {
#pragma unroll
    for (int l = 0; l < 2; l++) {
        int idx = tid + l * 256;
        int kr = idx >> 5;
        int nq = (idx & 31) << 2;
        float4 v = *(const float4*)(B + (size_t)(k0 + kr) * ldb + n0 + nq);
        if (bscale) {
            float s = bscale[(size_t)(k0 + kr) * bss];
            v.x *= s; v.y *= s; v.z *= s; v.w *= s;
        }
        *(float4*)(&Bs[kr][nq]) = v;
    }
}

// Inner product over one 16-deep K tile. acc[i][j] holds column pairs:
//   j=0: cols tx*4+{0,1}; j=1: tx*4+{2,3}; j=2: 64+tx*4+{0,1}; j=3: 64+tx*4+{2,3}
// rows: m0 + ty*8 + i.
__device__ __forceinline__ void mm_inner(float (*As)[132], float (*Bs)[128],
                                         int tx, int ty,
                                         unsigned long long acc[8][4]) {
#pragma unroll
    for (int kk = 0; kk < 16; kk++) {
        float4 a0 = *(const float4*)(&As[kk][ty * 8]);
        float4 a1 = *(const float4*)(&As[kk][ty * 8 + 4]);
        double2 bA = *(const double2*)(&Bs[kk][tx * 4]);
        double2 bB = *(const double2*)(&Bs[kk][64 + tx * 4]);
        unsigned long long bp[4];
        bp[0] = __double_as_longlong(bA.x);
        bp[1] = __double_as_longlong(bA.y);
        bp[2] = __double_as_longlong(bB.x);
        bp[3] = __double_as_longlong(bB.y);
        float av[8] = {a0.x, a0.y, a0.z, a0.w, a1.x, a1.y, a1.z, a1.w};
#pragma unroll
        for (int i = 0; i < 8; i++) {
            unsigned long long ap = dup2(av[i]);
#pragma unroll
            for (int j = 0; j < 4; j++) fma2(acc[i][j], ap, bp[j]);
        }
    }
}

// ---------------------------------------------------------------------------
// Batched GEMM: several independent GEMMs in one launch (fills the chip)
// ---------------------------------------------------------------------------
struct GemmDesc {
    const float* A;
    const float* B;
    const float* S;       // subtrahend for Chebyshev epilogue (epi=1)
    const float* bscale;  // diag matrix base for B row scaling (or null)
    const float* crow;    // diag matrix base for C row scaling (or null)
    float* C;
    int lda, ldb, lds, ldc;
    int bss, crs;         // diag strides (N+1)
    int K, mtiles, ntiles, tile_base;
    int transa, epi;      // epi: 0 = store (opt. row-scaled), 1 = 2*AB - S
};
struct BatchArgs { GemmDesc d[4]; int nd; };

__global__ __launch_bounds__(256, 2) void gemm_batched(BatchArgs args) {
    __shared__ __align__(16) float As[16][132];
    __shared__ __align__(16) float Bs[16][128];
    int tid = threadIdx.x;
    int tx = tid & 15, ty = tid >> 4;
    int bid = blockIdx.x;

    int di = 0;
#pragma unroll
    for (int i = 1; i < 4; i++)
        if (i < args.nd && bid >= args.d[i].tile_base) di = i;
    const GemmDesc& g = args.d[di];

    int tile = bid - g.tile_base;
    int bm = tile / g.ntiles;
    int bn = tile - bm * g.ntiles;
    int m0 = bm << 7, n0 = bn << 7;

    unsigned long long acc[8][4];
#pragma unroll
    for (int i = 0; i < 8; i++)
#pragma unroll
        for (int j = 0; j < 4; j++) acc[i][j] = 0ull;

    const float* A = g.A;
    const float* B = g.B;
    const float* bscale = g.bscale;
    int lda = g.lda, ldb = g.ldb, K = g.K, transa = g.transa, bss = g.bss;

#pragma unroll 1
    for (int k0 = 0; k0 < K; k0 += 16) {
        if (transa) ldA_t(As, A, lda, m0, k0, tid);
        else        ldA_n(As, A, lda, m0, k0, tid);
        ldB(Bs, B, ldb, n0, k0, bscale, bss, tid);
        __syncthreads();
        mm_inner(As, Bs, tx, ty, acc);
        __syncthreads();
    }

    float* C = g.C;
    int ldc = g.ldc;
    if (g.epi == 0) {
        const float* crow = g.crow;
        int crs = g.crs;
#pragma unroll
        for (int i = 0; i < 8; i++) {
            int mr = m0 + ty * 8 + i;
            float s = crow ? crow[(size_t)mr * crs] : 1.0f;
#pragma unroll
            for (int gi = 0; gi < 2; gi++) {
                float2 lo = un2(acc[i][2 * gi]);
                float2 hi = un2(acc[i][2 * gi + 1]);
                float4 v = make_float4(lo.x * s, lo.y * s, hi.x * s, hi.y * s);
                *(float4*)(C + (size_t)mr * ldc + n0 + gi * 64 + tx * 4) = v;
            }
        }
    } else {
        const float* S = g.S;
        int lds = g.lds;
#pragma unroll
        for (int i = 0; i < 8; i++) {
            int mr = m0 + ty * 8 + i;
#pragma unroll
            for (int gi = 0; gi < 2; gi++) {
                int col = n0 + gi * 64 + tx * 4;
                float4 sv = *(const float4*)(S + (size_t)mr * lds + col);
                float2 lo = un2(acc[i][2 * gi]);
                float2 hi = un2(acc[i][2 * gi + 1]);
                float4 v = make_float4(2.0f * lo.x - sv.x, 2.0f * lo.y - sv.y,
                                       2.0f * hi.x - sv.z, 2.0f * hi.y - sv.w);
                *(float4*)(C + (size_t)mr * ldc + col) = v;
            }
        }
    }
}

// ---------------------------------------------------------------------------
// Combine: y = relu(sum_c A_c @ W_c), one CTA per 128-row tile, loops channels
// ---------------------------------------------------------------------------
__global__ __launch_bounds__(256, 2) void combine_kernel(float* __restrict__ out) {
    __shared__ __align__(16) float As[16][132];
    __shared__ __align__(16) float Bs[16][128];
    int tid = threadIdx.x;
    int tx = tid & 15, ty = tid >> 4;
    int bid = blockIdx.x;

    const float* chp[8];
    int chl[8];
    const float* W;
    float* op;
    int nc, bm;
    if (bid < 16) {                 // order 0: rows 2048
        bm = bid; nc = 6; W = g_W0; op = out;
        chp[0] = g_X0cat;        chl[0] = 256;
        chp[1] = g_T10;          chl[1] = 256;
        chp[2] = g_T20;          chl[2] = 256;
        chp[3] = g_X0cat + 128;  chl[3] = 256;
        chp[4] = g_T10 + 128;    chl[4] = 256;
        chp[5] = g_T20 + 128;    chl[5] = 256;
    } else if (bid < 80) {          // order 1: rows 8192
        bm = bid - 16; nc = 8; W = g_W1; op = out + (size_t)CN0 * 128;
        chp[0] = g_X1cat;        chl[0] = 256;
        chp[1] = g_T1l;          chl[1] = 128;
        chp[2] = g_T2l;          chl[2] = 128;
        chp[3] = g_T1u;          chl[3] = 256;
        chp[4] = g_T2u;          chl[4] = 256;
        chp[5] = g_X1cat + 128;  chl[5] = 256;
        chp[6] = g_T1u + 128;    chl[6] = 256;
        chp[7] = g_T2u + 128;    chl[7] = 256;
    } else {                        // order 2: rows 4096
        bm = bid - 80; nc = 6; W = g_W2; op = out + (size_t)(CN0 + CN1) * 128;
        chp[0] = g_X2cat;        chl[0] = 256;
        chp[1] = g_T12;          chl[1] = 256;
        chp[2] = g_T22;          chl[2] = 256;
        chp[3] = g_X2cat + 128;  chl[3] = 256;
        chp[4] = g_T12 + 128;    chl[4] = 256;
        chp[5] = g_T22 + 128;    chl[5] = 256;
    }
    int m0 = bm << 7;

    unsigned long long acc[8][4];
#pragma unroll
    for (int i = 0; i < 8; i++)
#pragma unroll
        for (int j = 0; j < 4; j++) acc[i][j] = 0ull;

#pragma unroll 1
    for (int c = 0; c < nc; c++) {
        const float* A = chp[c];
        int lda = chl[c];
        const float* Bw = W + c * 16384;
#pragma unroll 1
        for (int k0 = 0; k0 < 128; k0 += 16) {
            ldA_n(As, A, lda, m0, k0, tid);
            ldB(Bs, Bw, 128, 0, k0, nullptr, 0, tid);
            __syncthreads();
            mm_inner(As, Bs, tx, ty, acc);
            __syncthreads();
        }
    }

#pragma unroll
    for (int i = 0; i < 8; i++) {
        int mr = m0 + ty * 8 + i;
#pragma unroll
        for (int gi = 0; gi < 2; gi++) {
            float2 lo = un2(acc[i][2 * gi]);
            float2 hi = un2(acc[i][2 * gi + 1]);
            float4 v = make_float4(fmaxf(lo.x, 0.0f), fmaxf(lo.y, 0.0f),
                                   fmaxf(hi.x, 0.0f), fmaxf(hi.y, 0.0f));
            *(float4*)(op + (size_t)mr * 128 + gi * 64 + tx * 4) = v;
        }
    }
}

// ---------------------------------------------------------------------------
// Prep kernels
// ---------------------------------------------------------------------------
// Repack w[i][o][c] (k innermost) -> W[c][i][o]
__global__ void pack_kernel(float* __restrict__ dst, const float* __restrict__ w, int nk) {
    int idx = blockIdx.x * 256 + threadIdx.x;   // over 128*128 (i,o) pairs
    if (idx < 16384) {
        for (int c = 0; c < nk; c++) dst[c * 16384 + idx] = w[idx * nk + c];
    }
}
// Copy [rows,128] (ld 128) -> dst (ld 256)
__global__ void copy_kernel(float* __restrict__ dst, const float* __restrict__ src, int rows) {
    int idx = blockIdx.x * 256 + threadIdx.x;
    int r = idx >> 5, q = (idx & 31) << 2;
    if (r < rows)
        *(float4*)(dst + (size_t)r * 256 + q) = *(const float4*)(src + (size_t)r * 128 + q);
}

// ---------------------------------------------------------------------------
// Host launcher
// ---------------------------------------------------------------------------
static GemmDesc mk(const float* A, int lda, int ta,
                   const float* B, int ldb, const float* bs, int bss,
                   float* C, int ldc,
                   const float* cr, int crs,
                   const float* S, int lds,
                   int K, int mt, int nt, int base, int epi) {
    GemmDesc g;
    g.A = A; g.lda = lda; g.transa = ta;
    g.B = B; g.ldb = ldb; g.bscale = bs; g.bss = bss;
    g.C = C; g.ldc = ldc;
    g.crow = cr; g.crs = crs;
    g.S = S; g.lds = lds;
    g.K = K; g.mtiles = mt; g.ntiles = nt; g.tile_base = base; g.epi = epi;
    return g;
}

extern "C" void kernel_launch(void* const* d_in, const int* in_sizes, int n_in,
                              void* d_out, int out_size) {
    const float* x0  = (const float*)d_in[0];
    const float* x1  = (const float*)d_in[1];
    const float* x2  = (const float*)d_in[2];
    const float* b1  = (const float*)d_in[3];
    const float* b2  = (const float*)d_in[4];
    const float* l0  = (const float*)d_in[5];
    const float* l1l = (const float*)d_in[6];
    const float* l1u = (const float*)d_in[7];
    const float* l2  = (const float*)d_in[8];
    const float* d1  = (const float*)d_in[9];    // diag matrix [N0,N0]
    const float* d3  = (const float*)d_in[10];   // diag matrix [N2,N2]
    const float* d5  = (const float*)d_in[11];   // diag matrix [N1,N1]
    const float* w0  = (const float*)d_in[12];
    const float* w1  = (const float*)d_in[13];
    const float* w2  = (const float*)d_in[14];
    float* out = (float*)d_out;
    (void)in_sizes; (void)n_in; (void)out_size;

    float *X0cat, *T10, *T20, *X1cat, *T1l, *T2l, *T1u, *T2u, *X2cat, *T12, *T22;
    float *W0, *W1, *W2;
    cudaGetSymbolAddress((void**)&X0cat, g_X0cat);
    cudaGetSymbolAddress((void**)&T10,   g_T10);
    cudaGetSymbolAddress((void**)&T20,   g_T20);
    cudaGetSymbolAddress((void**)&X1cat, g_X1cat);
    cudaGetSymbolAddress((void**)&T1l,   g_T1l);
    cudaGetSymbolAddress((void**)&T2l,   g_T2l);
    cudaGetSymbolAddress((void**)&T1u,   g_T1u);
    cudaGetSymbolAddress((void**)&T2u,   g_T2u);
    cudaGetSymbolAddress((void**)&X2cat, g_X2cat);
    cudaGetSymbolAddress((void**)&T12,   g_T12);
    cudaGetSymbolAddress((void**)&T22,   g_T22);
    cudaGetSymbolAddress((void**)&W0,    g_W0);
    cudaGetSymbolAddress((void**)&W1,    g_W1);
    cudaGetSymbolAddress((void**)&W2,    g_W2);

    // Prep: weight repack + feature copies into concatenated panels
    pack_kernel<<<64, 256>>>(W0, w0, 6);
    pack_kernel<<<64, 256>>>(W1, w1, 8);
    pack_kernel<<<64, 256>>>(W2, w2, 6);
    copy_kernel<<<CN0 * 32 / 256, 256>>>(X0cat,       x0, CN0);  // X0cat[:, :128] = x0
    copy_kernel<<<CN1 * 32 / 256, 256>>>(X1cat,       x1, CN1);  // X1cat[:, :128] = x1
    copy_kernel<<<CN2 * 32 / 256, 256>>>(X2cat + 128, x2, CN2);  // X2cat[:,128:]  = x2

    // Wave 1: projections (all independent) — 112 CTAs
    BatchArgs ba; ba.nd = 3;
    // x0p = d1_inv * (b1 @ x1) -> X0cat[:,128:]
    ba.d[0] = mk(b1, CN1, 0, x1, 128, nullptr, 0, X0cat + 128, 256,
                 d1, CN0 + 1, nullptr, 0, CN1, 16, 1, 0, 0);
    // x1p = b2 @ (d3 * x2) -> X1cat[:,128:]
    ba.d[1] = mk(b2, CN2, 0, x2, 128, d3, CN2 + 1, X1cat + 128, 256,
                 nullptr, 0, nullptr, 0, CN2, 64, 1, 16, 0);
    // x2n = b2^T @ (d5_pinv * x1) -> X2cat[:,:128]
    ba.d[2] = mk(b2, CN2, 1, x1, 128, d5, CN1 + 1, X2cat, 256,
                 nullptr, 0, nullptr, 0, CN1, 32, 1, 80, 0);
    gemm_batched<<<112, 256>>>(ba);

    // Wave 2: first Chebyshev terms T1 = L @ X — 288 CTAs
    BatchArgs bb; bb.nd = 4;
    bb.d[0] = mk(l0,  CN0, 0, X0cat, 256, nullptr, 0, T10, 256,
                 nullptr, 0, nullptr, 0, CN0, 16, 2, 0, 0);
    bb.d[1] = mk(l1l, CN1, 0, x1,    128, nullptr, 0, T1l, 128,
                 nullptr, 0, nullptr, 0, CN1, 64, 1, 32, 0);
    bb.d[2] = mk(l1u, CN1, 0, X1cat, 256, nullptr, 0, T1u, 256,
                 nullptr, 0, nullptr, 0, CN1, 64, 2, 96, 0);
    bb.d[3] = mk(l2,  CN2, 0, X2cat, 256, nullptr, 0, T12, 256,
                 nullptr, 0, nullptr, 0, CN2, 32, 2, 224, 0);
    gemm_batched<<<288, 256>>>(bb);

    // Wave 3: second Chebyshev terms T2 = 2 L T1 - X — 288 CTAs
    BatchArgs bc; bc.nd = 4;
    bc.d[0] = mk(l0,  CN0, 0, T10, 256, nullptr, 0, T20, 256,
                 nullptr, 0, X0cat, 256, CN0, 16, 2, 0, 1);
    bc.d[1] = mk(l1l, CN1, 0, T1l, 128, nullptr, 0, T2l, 128,
                 nullptr, 0, x1, 128, CN1, 64, 1, 32, 1);
    bc.d[2] = mk(l1u, CN1, 0, T1u, 256, nullptr, 0, T2u, 256,
                 nullptr, 0, X1cat, 256, CN1, 64, 2, 96, 1);
    bc.d[3] = mk(l2,  CN2, 0, T12, 256, nullptr, 0, T22, 256,
                 nullptr, 0, X2cat, 256, CN2, 32, 2, 224, 1);
    gemm_batched<<<288, 256>>>(bc);

    // Wave 4: channel combine + relu — 112 CTAs
    combine_kernel<<<112, 256>>>(out);
}

// round 11
// speedup vs baseline: 1.6663x; 1.6604x over previous
#include <cuda_runtime.h>
#include <cuda_bf16.h>
#include <cstdint>

#define CN0 2048
#define CN1 8192
#define CN2 4096

// ---------------------------------------------------------------------------
// Scratch (device globals — no allocation allowed)
// ---------------------------------------------------------------------------
__device__ float g_X0cat[CN0 * 256];   // [x0 | x0p]
__device__ float g_T10[CN0 * 256];
__device__ float g_T20[CN0 * 256];
__device__ float g_X1cat[CN1 * 256];   // [x1 | x1p]
__device__ float g_T1l[CN1 * 128];
__device__ float g_T2l[CN1 * 128];
__device__ float g_T1u[CN1 * 256];
__device__ float g_T2u[CN1 * 256];
__device__ float g_X2cat[CN2 * 256];   // [x2n | x2]
__device__ float g_T12[CN2 * 256];
__device__ float g_T22[CN2 * 256];
__device__ float g_W0[6 * 16384];      // repacked [c][i][o]
__device__ float g_W1[8 * 16384];
__device__ float g_W2[6 * 16384];

// ---------------------------------------------------------------------------
// Helpers (sm_80-level features ONLY — harness compiles for plain sm_103)
// ---------------------------------------------------------------------------
__device__ __forceinline__ uint32_t smem_u32(const void* p) {
    uint32_t a;
    asm("{ .reg .u64 t; cvta.to.shared.u64 t, %1; cvt.u32.u64 %0, t; }"
        : "=r"(a) : "l"(p));
    return a;
}
__device__ __forceinline__ uint32_t swz(uint32_t off) {
    return off ^ ((off >> 3) & 0x70u);   // SW128 swizzle for 128B rows
}
__device__ __forceinline__ void ldm4(uint32_t addr, uint32_t r[4]) {
    asm volatile("ldmatrix.sync.aligned.m8n8.x4.shared.b16 {%0,%1,%2,%3}, [%4];"
                 : "=r"(r[0]), "=r"(r[1]), "=r"(r[2]), "=r"(r[3]) : "r"(addr));
}
__device__ __forceinline__ void mma16816(float d[4], const uint32_t a[4],
                                         uint32_t b0, uint32_t b1) {
    asm volatile("mma.sync.aligned.m16n8k16.row.col.f32.bf16.bf16.f32 "
                 "{%0,%1,%2,%3}, {%4,%5,%6,%7}, {%8,%9}, {%0,%1,%2,%3};"
                 : "+f"(d[0]), "+f"(d[1]), "+f"(d[2]), "+f"(d[3])
                 : "r"(a[0]), "r"(a[1]), "r"(a[2]), "r"(a[3]), "r"(b0), "r"(b1));
}

// ---------------------------------------------------------------------------
// bf16 hi/lo split + swizzled STS
// ---------------------------------------------------------------------------
__device__ __forceinline__ void split8(const float4& v0, const float4& v1,
                                       uint4& hi, uint4& lo) {
    float a[8] = {v0.x, v0.y, v0.z, v0.w, v1.x, v1.y, v1.z, v1.w};
    uint32_t h[4], l[4];
#pragma unroll
    for (int p = 0; p < 4; p++) {
        __nv_bfloat162 hb = __floats2bfloat162_rn(a[2 * p], a[2 * p + 1]);
        float hx = __bfloat162float(hb.x), hy = __bfloat162float(hb.y);
        __nv_bfloat162 lb = __floats2bfloat162_rn(a[2 * p] - hx, a[2 * p + 1] - hy);
        h[p] = *(uint32_t*)&hb;
        l[p] = *(uint32_t*)&lb;
    }
    hi = make_uint4(h[0], h[1], h[2], h[3]);
    lo = make_uint4(l[0], l[1], l[2], l[3]);
}
__device__ __forceinline__ void sts128(char* base, uint32_t off, const uint4& v) {
    *(uint4*)(base + swz(off)) = v;
}

// ---------------------------------------------------------------------------
// Chunk loaders: A [128m x 64k], B [128n x 64k], K-major bf16 hi/lo, 256 thr
// ---------------------------------------------------------------------------
__device__ __forceinline__ void load_A_n(char* hi, char* lo, const float* __restrict__ A,
                                         int lda, int m0, int k0, int t) {
    const float* Ab = A + (size_t)m0 * lda + k0;
#pragma unroll
    for (int l = 0; l < 4; l++) {
        int idx = t + l * 256;           // 1024 items: (m, kg8)
        int m = idx >> 3, kg = idx & 7;
        const float* p = Ab + (size_t)m * lda + kg * 8;
        float4 v0 = *(const float4*)p;
        float4 v1 = *(const float4*)(p + 4);
        uint4 h, lw;
        split8(v0, v1, h, lw);
        uint32_t off = (uint32_t)(m * 128 + kg * 16);
        sts128(hi, off, h);
        sts128(lo, off, lw);
    }
}
__device__ __forceinline__ void load_A_t(char* hi, char* lo, const float* __restrict__ A,
                                         int lda, int m0, int k0, int t) {
    int m = t & 127;
    const float* Ab = A + (size_t)k0 * lda + m0 + m;
#pragma unroll
    for (int l = 0; l < 4; l++) {
        int kg = (t >> 7) + l * 2;
        const float* p = Ab + (size_t)kg * 8 * lda;
        float4 v0, v1;
        v0.x = p[0];
        v0.y = p[(size_t)lda];
        v0.z = p[(size_t)2 * lda];
        v0.w = p[(size_t)3 * lda];
        v1.x = p[(size_t)4 * lda];
        v1.y = p[(size_t)5 * lda];
        v1.z = p[(size_t)6 * lda];
        v1.w = p[(size_t)7 * lda];
        uint4 h, lw;
        split8(v0, v1, h, lw);
        uint32_t off = (uint32_t)(m * 128 + kg * 16);
        sts128(hi, off, h);
        sts128(lo, off, lw);
    }
}
__device__ __forceinline__ void load_B(char* bhi, char* blo, const float* __restrict__ B,
                                       int ldb, int k0, const float* __restrict__ bscale,
                                       int bss, int t) {
    int n = t & 127;
    const float* Bb = B + (size_t)k0 * ldb + n;
#pragma unroll
    for (int l = 0; l < 4; l++) {
        int kg = (t >> 7) + l * 2;
        const float* p = Bb + (size_t)kg * 8 * ldb;
        float4 v0, v1;
        v0.x = p[0];
        v0.y = p[(size_t)ldb];
        v0.z = p[(size_t)2 * ldb];
        v0.w = p[(size_t)3 * ldb];
        v1.x = p[(size_t)4 * ldb];
        v1.y = p[(size_t)5 * ldb];
        v1.z = p[(size_t)6 * ldb];
        v1.w = p[(size_t)7 * ldb];
        if (bscale) {
            const float* sp = bscale + (size_t)(k0 + kg * 8) * bss;
            v0.x *= sp[0];
            v0.y *= sp[(size_t)bss];
            v0.z *= sp[(size_t)2 * bss];
            v0.w *= sp[(size_t)3 * bss];
            v1.x *= sp[(size_t)4 * bss];
            v1.y *= sp[(size_t)5 * bss];
            v1.z *= sp[(size_t)6 * bss];
            v1.w *= sp[(size_t)7 * bss];
        }
        uint4 h, lw;
        split8(v0, v1, h, lw);
        uint32_t off = (uint32_t)(n * 128 + kg * 16);
        sts128(bhi, off, h);
        sts128(blo, off, lw);
    }
}

// ---------------------------------------------------------------------------
// Batched GEMM descriptors
// ---------------------------------------------------------------------------
struct GemmDesc {
    const float* A;
    const float* B;
    const float* S;
    const float* bscale;
    const float* crow;
    const float* Achan[8];
    float* C;
    int Alda[8];
    int lda, ldb, lds, ldc, bss, crs;
    int K, ntiles, tile_base, transa, epi, nch;  // epi: 0=scale, 1=2AB-S, 2=relu
};
struct BatchArgs { GemmDesc d[4]; int nd; };

__device__ __forceinline__ void load_chunk(char* stg, const GemmDesc& g,
                                           int m0, int n0, int k0, int t) {
    char* aHi = stg;
    char* aLo = stg + 16384;
    char* bHi = stg + 32768;
    char* bLo = stg + 49152;
    if (g.nch) {
        int c = k0 >> 7;
        int kin = k0 & 127;
        load_A_n(aHi, aLo, g.Achan[c], g.Alda[c], m0, kin, t);
        load_B(bHi, bLo, g.B + (size_t)c * 16384, 128, kin, nullptr, 0, t);
    } else {
        if (g.transa) load_A_t(aHi, aLo, g.A, g.lda, m0, k0, t);
        else          load_A_n(aHi, aLo, g.A, g.lda, m0, k0, t);
        load_B(bHi, bLo, g.B + n0, g.ldb, k0, g.bscale, g.bss, t);
    }
}

// Inner compute over one K=64 chunk: warp tile 32m x 64n, 3-product bf16 comp.
__device__ __forceinline__ void compute_chunk(uint32_t sAh, uint32_t sAl,
                                              uint32_t sBh, uint32_t sBl,
                                              int wm, int wn, int lane,
                                              float acc[2][8][4]) {
#pragma unroll
    for (int kk = 0; kk < 4; kk++) {
        uint32_t ah[2][4], al[2][4];
#pragma unroll
        for (int mt = 0; mt < 2; mt++) {
            uint32_t off = (uint32_t)((wm * 32 + mt * 16 + (lane & 15)) * 128
                                      + kk * 32 + ((lane >> 4) << 4));
            uint32_t so = swz(off);
            ldm4(sAh + so, ah[mt]);
            ldm4(sAl + so, al[mt]);
        }
        uint32_t bh[4][4], bl[4][4];
#pragma unroll
        for (int ng = 0; ng < 4; ng++) {
            int r = lane & 7, part = lane >> 3;
            int n = wn * 64 + ng * 16 + r + ((part >> 1) << 3);
            uint32_t off = (uint32_t)(n * 128 + kk * 32 + ((part & 1) << 4));
            uint32_t so = swz(off);
            ldm4(sBh + so, bh[ng]);
            ldm4(sBl + so, bl[ng]);
        }
#pragma unroll
        for (int mt = 0; mt < 2; mt++)
#pragma unroll
            for (int ng = 0; ng < 4; ng++)
#pragma unroll
                for (int h = 0; h < 2; h++) {
                    int nt = ng * 2 + h;
                    mma16816(acc[mt][nt], ah[mt], bh[ng][h * 2], bh[ng][h * 2 + 1]);
                    mma16816(acc[mt][nt], ah[mt], bl[ng][h * 2], bl[ng][h * 2 + 1]);
                    mma16816(acc[mt][nt], al[mt], bh[ng][h * 2], bh[ng][h * 2 + 1]);
                }
    }
}

#define STAGE_BYTES 65536
#define SMEM_BYTES (2 * STAGE_BYTES + 1024)

__global__ __launch_bounds__(256, 1) void gemm_mma(BatchArgs args) {
    extern __shared__ char smem_raw[];
    uint32_t sb = smem_u32(smem_raw);
    uint32_t al1k = (sb + 1023u) & ~1023u;
    char* st0 = smem_raw + (al1k - sb);
    uint32_t sb0 = al1k;

    int t = threadIdx.x;
    int lane = t & 31;
    int warp = t >> 5;
    int wm = warp >> 1, wn = warp & 1;
    int bid = blockIdx.x;

    int di = 0;
#pragma unroll
    for (int i = 1; i < 4; i++)
        if (i < args.nd && bid >= args.d[i].tile_base) di = i;
    const GemmDesc& g = args.d[di];

    int tile = bid - g.tile_base;
    int bm = tile / g.ntiles;
    int bn = tile - bm * g.ntiles;
    int m0 = bm << 7, n0 = bn << 7;

    float acc[2][8][4];
#pragma unroll
    for (int i = 0; i < 2; i++)
#pragma unroll
        for (int j = 0; j < 8; j++)
#pragma unroll
            for (int k = 0; k < 4; k++) acc[i][j][k] = 0.0f;

    int NC = g.K >> 6;

    load_chunk(st0, g, m0, n0, 0, t);
    __syncthreads();

#pragma unroll 1
    for (int ci = 0; ci < NC; ci++) {
        int cur = ci & 1;
        if (ci + 1 < NC)
            load_chunk(st0 + ((ci + 1) & 1) * STAGE_BYTES, g, m0, n0, (ci + 1) << 6, t);
        uint32_t s = sb0 + cur * STAGE_BYTES;
        compute_chunk(s, s + 16384, s + 32768, s + 49152, wm, wn, lane, acc);
        __syncthreads();
    }

    // Epilogue: acc[mt][nt] rows r0 = m0+wm*32+mt*16+(lane>>2), r1 = r0+8;
    //           cols c = n0+wn*64+nt*8+(lane&3)*2
    int ldc = g.ldc;
#pragma unroll
    for (int mt = 0; mt < 2; mt++) {
        int r0 = m0 + wm * 32 + mt * 16 + (lane >> 2);
        int r1 = r0 + 8;
        float s0 = 1.0f, s1 = 1.0f;
        if (g.epi == 0 && g.crow) {
            s0 = g.crow[(size_t)r0 * g.crs];
            s1 = g.crow[(size_t)r1 * g.crs];
        }
        float* C0 = g.C + (size_t)r0 * ldc;
        float* C1 = g.C + (size_t)r1 * ldc;
        const float* S0 = nullptr;
        const float* S1 = nullptr;
        if (g.epi == 1) {
            S0 = g.S + (size_t)r0 * g.lds;
            S1 = g.S + (size_t)r1 * g.lds;
        }
#pragma unroll
        for (int nt = 0; nt < 8; nt++) {
            int c = n0 + wn * 64 + nt * 8 + ((lane & 3) << 1);
            float d0 = acc[mt][nt][0], d1 = acc[mt][nt][1];
            float d2 = acc[mt][nt][2], d3 = acc[mt][nt][3];
            if (g.epi == 0) {
                *(float2*)(C0 + c) = make_float2(d0 * s0, d1 * s0);
                *(float2*)(C1 + c) = make_float2(d2 * s1, d3 * s1);
            } else if (g.epi == 1) {
                float2 sv0 = *(const float2*)(S0 + c);
                float2 sv1 = *(const float2*)(S1 + c);
                *(float2*)(C0 + c) = make_float2(2.f * d0 - sv0.x, 2.f * d1 - sv0.y);
                *(float2*)(C1 + c) = make_float2(2.f * d2 - sv1.x, 2.f * d3 - sv1.y);
            } else {
                *(float2*)(C0 + c) = make_float2(fmaxf(d0, 0.f), fmaxf(d1, 0.f));
                *(float2*)(C1 + c) = make_float2(fmaxf(d2, 0.f), fmaxf(d3, 0.f));
            }
        }
    }
}

// ---------------------------------------------------------------------------
// Prep kernels
// ---------------------------------------------------------------------------
__global__ void pack_kernel(float* __restrict__ dst, const float* __restrict__ w, int nk) {
    int idx = blockIdx.x * 256 + threadIdx.x;
    if (idx < 16384) {
        for (int c = 0; c < nk; c++) dst[c * 16384 + idx] = w[idx * nk + c];
    }
}
__global__ void copy_kernel(float* __restrict__ dst, const float* __restrict__ src, int rows) {
    int idx = blockIdx.x * 256 + threadIdx.x;
    int r = idx >> 5, q = (idx & 31) << 2;
    if (r < rows)
        *(float4*)(dst + (size_t)r * 256 + q) = *(const float4*)(src + (size_t)r * 128 + q);
}

// ---------------------------------------------------------------------------
// Host launcher
// ---------------------------------------------------------------------------
static GemmDesc mk(const float* A, int lda, int ta,
                   const float* B, int ldb, const float* bs, int bss,
                   float* C, int ldc,
                   const float* cr, int crs,
                   const float* S, int lds,
                   int K, int ntiles, int base, int epi) {
    GemmDesc g{};
    g.A = A; g.lda = lda; g.transa = ta;
    g.B = B; g.ldb = ldb; g.bscale = bs; g.bss = bss;
    g.C = C; g.ldc = ldc;
    g.crow = cr; g.crs = crs;
    g.S = S; g.lds = lds;
    g.K = K; g.ntiles = ntiles; g.tile_base = base; g.epi = epi; g.nch = 0;
    return g;
}

extern "C" void kernel_launch(void* const* d_in, const int* in_sizes, int n_in,
                              void* d_out, int out_size) {
    const float* x0  = (const float*)d_in[0];
    const float* x1  = (const float*)d_in[1];
    const float* x2  = (const float*)d_in[2];
    const float* b1  = (const float*)d_in[3];
    const float* b2  = (const float*)d_in[4];
    const float* l0  = (const float*)d_in[5];
    const float* l1l = (const float*)d_in[6];
    const float* l1u = (const float*)d_in[7];
    const float* l2  = (const float*)d_in[8];
    const float* d1  = (const float*)d_in[9];
    const float* d3  = (const float*)d_in[10];
    const float* d5  = (const float*)d_in[11];
    const float* w0  = (const float*)d_in[12];
    const float* w1  = (const float*)d_in[13];
    const float* w2  = (const float*)d_in[14];
    float* out = (float*)d_out;
    (void)in_sizes; (void)n_in; (void)out_size;

    float *X0cat, *T10, *T20, *X1cat, *T1l, *T2l, *T1u, *T2u, *X2cat, *T12, *T22;
    float *W0, *W1, *W2;
    cudaGetSymbolAddress((void**)&X0cat, g_X0cat);
    cudaGetSymbolAddress((void**)&T10,   g_T10);
    cudaGetSymbolAddress((void**)&T20,   g_T20);
    cudaGetSymbolAddress((void**)&X1cat, g_X1cat);
    cudaGetSymbolAddress((void**)&T1l,   g_T1l);
    cudaGetSymbolAddress((void**)&T2l,   g_T2l);
    cudaGetSymbolAddress((void**)&T1u,   g_T1u);
    cudaGetSymbolAddress((void**)&T2u,   g_T2u);
    cudaGetSymbolAddress((void**)&X2cat, g_X2cat);
    cudaGetSymbolAddress((void**)&T12,   g_T12);
    cudaGetSymbolAddress((void**)&T22,   g_T22);
    cudaGetSymbolAddress((void**)&W0,    g_W0);
    cudaGetSymbolAddress((void**)&W1,    g_W1);
    cudaGetSymbolAddress((void**)&W2,    g_W2);

    cudaFuncSetAttribute(gemm_mma, cudaFuncAttributeMaxDynamicSharedMemorySize, SMEM_BYTES);

    // Prep
    pack_kernel<<<64, 256>>>(W0, w0, 6);
    pack_kernel<<<64, 256>>>(W1, w1, 8);
    pack_kernel<<<64, 256>>>(W2, w2, 6);
    copy_kernel<<<CN0 * 32 / 256, 256>>>(X0cat,       x0, CN0);
    copy_kernel<<<CN1 * 32 / 256, 256>>>(X1cat,       x1, CN1);
    copy_kernel<<<CN2 * 32 / 256, 256>>>(X2cat + 128, x2, CN2);

    // Wave 1: projections — 112 CTAs
    BatchArgs ba; ba.nd = 3;
    ba.d[0] = mk(b1, CN1, 0, x1, 128, nullptr, 0, X0cat + 128, 256,
                 d1, CN0 + 1, nullptr, 0, CN1, 1, 0, 0);
    ba.d[1] = mk(b2, CN2, 0, x2, 128, d3, CN2 + 1, X1cat + 128, 256,
                 nullptr, 0, nullptr, 0, CN2, 1, 16, 0);
    ba.d[2] = mk(b2, CN2, 1, x1, 128, d5, CN1 + 1, X2cat, 256,
                 nullptr, 0, nullptr, 0, CN1, 1, 80, 0);
    gemm_mma<<<112, 256, SMEM_BYTES>>>(ba);

    // Wave 2: T1 = L @ X — 288 CTAs
    BatchArgs bb; bb.nd = 4;
    bb.d[0] = mk(l0,  CN0, 0, X0cat, 256, nullptr, 0, T10, 256,
                 nullptr, 0, nullptr, 0, CN0, 2, 0, 0);
    bb.d[1] = mk(l1l, CN1, 0, x1,    128, nullptr, 0, T1l, 128,
                 nullptr, 0, nullptr, 0, CN1, 1, 32, 0);
    bb.d[2] = mk(l1u, CN1, 0, X1cat, 256, nullptr, 0, T1u, 256,
                 nullptr, 0, nullptr, 0, CN1, 2, 96, 0);
    bb.d[3] = mk(l2,  CN2, 0, X2cat, 256, nullptr, 0, T12, 256,
                 nullptr, 0, nullptr, 0, CN2, 2, 224, 0);
    gemm_mma<<<288, 256, SMEM_BYTES>>>(bb);

    // Wave 3: T2 = 2 L T1 - X — 288 CTAs
    BatchArgs bc; bc.nd = 4;
    bc.d[0] = mk(l0,  CN0, 0, T10, 256, nullptr, 0, T20, 256,
                 nullptr, 0, X0cat, 256, CN0, 2, 0, 1);
    bc.d[1] = mk(l1l, CN1, 0, T1l, 128, nullptr, 0, T2l, 128,
                 nullptr, 0, x1, 128, CN1, 1, 32, 1);
    bc.d[2] = mk(l1u, CN1, 0, T1u, 256, nullptr, 0, T2u, 256,
                 nullptr, 0, X1cat, 256, CN1, 2, 96, 1);
    bc.d[3] = mk(l2,  CN2, 0, T12, 256, nullptr, 0, T22, 256,
                 nullptr, 0, X2cat, 256, CN2, 2, 224, 1);
    gemm_mma<<<288, 256, SMEM_BYTES>>>(bc);

    // Wave 4: combine + relu — 112 CTAs (multi-channel K)
    BatchArgs bd; bd.nd = 3;
    {
        GemmDesc g = mk(nullptr, 0, 0, W0, 128, nullptr, 0, out, 128,
                        nullptr, 0, nullptr, 0, 6 * 128, 1, 0, 2);
        g.nch = 6;
        const float* ch[6] = {X0cat, T10, T20, X0cat + 128, T10 + 128, T20 + 128};
        for (int c = 0; c < 6; c++) { g.Achan[c] = ch[c]; g.Alda[c] = 256; }
        bd.d[0] = g;
    }
    {
        GemmDesc g = mk(nullptr, 0, 0, W1, 128, nullptr, 0, out + (size_t)CN0 * 128, 128,
                        nullptr, 0, nullptr, 0, 8 * 128, 1, 16, 2);
        g.nch = 8;
        const float* ch[8] = {X1cat, T1l, T2l, T1u, T2u,
                              X1cat + 128, T1u + 128, T2u + 128};
        int ld[8] = {256, 128, 128, 256, 256, 256, 256, 256};
        for (int c = 0; c < 8; c++) { g.Achan[c] = ch[c]; g.Alda[c] = ld[c]; }
        bd.d[1] = g;
    }
    {
        GemmDesc g = mk(nullptr, 0, 0, W2, 128, nullptr, 0,
                        out + (size_t)(CN0 + CN1) * 128, 128,
                        nullptr, 0, nullptr, 0, 6 * 128, 1, 80, 2);
        g.nch = 6;
        const float* ch[6] = {X2cat, T12, T22, X2cat + 128, T12 + 128, T22 + 128};
        for (int c = 0; c < 6; c++) { g.Achan[c] = ch[c]; g.Alda[c] = 256; }
        bd.d[2] = g;
    }
    gemm_mma<<<112, 256, SMEM_BYTES>>>(bd);
}

// round 12
// speedup vs baseline: 2.4384x; 1.4634x over previous
#include <cuda_runtime.h>
#include <cuda_bf16.h>
#include <cstdint>

#define CN0 2048
#define CN1 8192
#define CN2 4096

// ---------------------------------------------------------------------------
// Scratch (device globals — no allocation allowed)
// ---------------------------------------------------------------------------
__device__ float g_X0cat[CN0 * 256];   // [x0 | x0p]
__device__ float g_T10[CN0 * 256];
__device__ float g_T20[CN0 * 256];
__device__ float g_X1cat[CN1 * 256];   // [x1 | x1p]
__device__ float g_T1l[CN1 * 128];
__device__ float g_T2l[CN1 * 128];
__device__ float g_T1u[CN1 * 256];
__device__ float g_T2u[CN1 * 256];
__device__ float g_X2cat[CN2 * 256];   // [x2n | x2]
__device__ float g_T12[CN2 * 256];
__device__ float g_T22[CN2 * 256];
__device__ float g_W0[6 * 16384];      // repacked [c][i][o]
__device__ float g_W1[8 * 16384];
__device__ float g_W2[6 * 16384];
__device__ float g_x1s[CN1 * 128];     // d5_pinv * x1 (pre-scaled)
__device__ float g_x2s[CN2 * 128];     // d3 * x2 (pre-scaled)

// ---------------------------------------------------------------------------
// Helpers (sm_80-level features ONLY — harness compiles for plain sm_103)
// ---------------------------------------------------------------------------
__device__ __forceinline__ uint32_t smem_u32(const void* p) {
    uint32_t a;
    asm("{ .reg .u64 t; cvta.to.shared.u64 t, %1; cvt.u32.u64 %0, t; }"
        : "=r"(a) : "l"(p));
    return a;
}
__device__ __forceinline__ uint32_t swz(uint32_t off) {
    return off ^ ((off >> 3) & 0x70u);   // SW128 swizzle for 128B rows
}
__device__ __forceinline__ void ldm4(uint32_t addr, uint32_t r[4]) {
    asm volatile("ldmatrix.sync.aligned.m8n8.x4.shared.b16 {%0,%1,%2,%3}, [%4];"
                 : "=r"(r[0]), "=r"(r[1]), "=r"(r[2]), "=r"(r[3]) : "r"(addr));
}
__device__ __forceinline__ void mma16816(float d[4], const uint32_t a[4],
                                         uint32_t b0, uint32_t b1) {
    asm volatile("mma.sync.aligned.m16n8k16.row.col.f32.bf16.bf16.f32 "
                 "{%0,%1,%2,%3}, {%4,%5,%6,%7}, {%8,%9}, {%0,%1,%2,%3};"
                 : "+f"(d[0]), "+f"(d[1]), "+f"(d[2]), "+f"(d[3])
                 : "r"(a[0]), "r"(a[1]), "r"(a[2]), "r"(a[3]), "r"(b0), "r"(b1));
}

// ---------------------------------------------------------------------------
// bf16 hi/lo split + swizzled STS
// ---------------------------------------------------------------------------
__device__ __forceinline__ void split8(const float4& v0, const float4& v1,
                                       uint4& hi, uint4& lo) {
    float a[8] = {v0.x, v0.y, v0.z, v0.w, v1.x, v1.y, v1.z, v1.w};
    uint32_t h[4], l[4];
#pragma unroll
    for (int p = 0; p < 4; p++) {
        __nv_bfloat162 hb = __floats2bfloat162_rn(a[2 * p], a[2 * p + 1]);
        float hx = __bfloat162float(hb.x), hy = __bfloat162float(hb.y);
        __nv_bfloat162 lb = __floats2bfloat162_rn(a[2 * p] - hx, a[2 * p + 1] - hy);
        h[p] = *(uint32_t*)&hb;
        l[p] = *(uint32_t*)&lb;
    }
    hi = make_uint4(h[0], h[1], h[2], h[3]);
    lo = make_uint4(l[0], l[1], l[2], l[3]);
}
__device__ __forceinline__ void sts128(char* base, uint32_t off, const uint4& v) {
    *(uint4*)(base + swz(off)) = v;
}

// ---------------------------------------------------------------------------
// Staged chunk loaders: ldg (gmem -> regs) / sts (split -> smem), 256 threads
// A tile [128m x 64k], B tile [128n x 64k], K-major bf16 hi/lo panels.
// ---------------------------------------------------------------------------
// A normal (row-major, K contiguous): idx = t+256l -> m = idx>>3, kg = idx&7
__device__ __forceinline__ void ldgA_n(float4* st, const float* __restrict__ A,
                                       int lda, int m0, int k0, int t) {
    const float* Ab = A + (size_t)m0 * lda + k0;
#pragma unroll
    for (int l = 0; l < 4; l++) {
        int idx = t + l * 256;
        int m = idx >> 3, kg = idx & 7;
        const float* p = Ab + (size_t)m * lda + kg * 8;
        st[2 * l]     = *(const float4*)p;
        st[2 * l + 1] = *(const float4*)(p + 4);
    }
}
__device__ __forceinline__ void stsA_n(char* hi, char* lo, const float4* st, int t) {
#pragma unroll
    for (int l = 0; l < 4; l++) {
        int idx = t + l * 256;
        int m = idx >> 3, kg = idx & 7;
        uint4 h, lw;
        split8(st[2 * l], st[2 * l + 1], h, lw);
        uint32_t off = (uint32_t)(m * 128 + kg * 16);
        sts128(hi, off, h);
        sts128(lo, off, lw);
    }
}
// Transposed-A / B gather pattern: fixed m(or n) = t&127, kg = (t>>7)+2l
__device__ __forceinline__ void ldg_kt(float4* st, const float* __restrict__ A,
                                       int lda, int col0, int k0, int t) {
    int m = t & 127;
    const float* Ab = A + (size_t)k0 * lda + col0 + m;
#pragma unroll
    for (int l = 0; l < 4; l++) {
        int kg = (t >> 7) + l * 2;
        const float* p = Ab + (size_t)kg * 8 * lda;
        float4 v0, v1;
        v0.x = p[0];
        v0.y = p[(size_t)lda];
        v0.z = p[(size_t)2 * lda];
        v0.w = p[(size_t)3 * lda];
        v1.x = p[(size_t)4 * lda];
        v1.y = p[(size_t)5 * lda];
        v1.z = p[(size_t)6 * lda];
        v1.w = p[(size_t)7 * lda];
        st[2 * l]     = v0;
        st[2 * l + 1] = v1;
    }
}
__device__ __forceinline__ void sts_kt(char* hi, char* lo, const float4* st, int t) {
    int m = t & 127;
#pragma unroll
    for (int l = 0; l < 4; l++) {
        int kg = (t >> 7) + l * 2;
        uint4 h, lw;
        split8(st[2 * l], st[2 * l + 1], h, lw);
        uint32_t off = (uint32_t)(m * 128 + kg * 16);
        sts128(hi, off, h);
        sts128(lo, off, lw);
    }
}

// ---------------------------------------------------------------------------
// Batched GEMM descriptors
// ---------------------------------------------------------------------------
struct GemmDesc {
    const float* A;
    const float* B;
    const float* S;
    const float* crow;
    const float* Achan[8];
    float* C;
    int Alda[8];
    int lda, ldb, lds, ldc, crs;
    int K, ntiles, tile_base, transa, epi, nch;  // epi: 0=scale, 1=2AB-S, 2=relu
};
struct BatchArgs { GemmDesc d[4]; int nd; };

__device__ __forceinline__ void ldg_chunk(float4* stA, float4* stB, const GemmDesc& g,
                                          int m0, int n0, int k0, int t) {
    if (g.nch) {
        int c = k0 >> 7, kin = k0 & 127;
        ldgA_n(stA, g.Achan[c], g.Alda[c], m0, kin, t);
        ldg_kt(stB, g.B + (size_t)c * 16384, 128, 0, kin, t);
    } else if (g.transa) {
        ldg_kt(stA, g.A, g.lda, m0, k0, t);
        ldg_kt(stB, g.B, g.ldb, n0, k0, t);
    } else {
        ldgA_n(stA, g.A, g.lda, m0, k0, t);
        ldg_kt(stB, g.B, g.ldb, n0, k0, t);
    }
}
__device__ __forceinline__ void sts_chunk(char* stg, const float4* stA, const float4* stB,
                                          int t, int amode) {
    char* aHi = stg;
    char* aLo = stg + 16384;
    char* bHi = stg + 32768;
    char* bLo = stg + 49152;
    if (amode) sts_kt(aHi, aLo, stA, t);
    else       stsA_n(aHi, aLo, stA, t);
    sts_kt(bHi, bLo, stB, t);
}

// Inner compute over one K=64 chunk: warp tile 32m x 64n, 3-product bf16 comp.
__device__ __forceinline__ void compute_chunk(uint32_t sAh, uint32_t sAl,
                                              uint32_t sBh, uint32_t sBl,
                                              int wm, int wn, int lane,
                                              float acc[2][8][4]) {
#pragma unroll
    for (int kk = 0; kk < 4; kk++) {
        uint32_t ah[2][4], al[2][4];
#pragma unroll
        for (int mt = 0; mt < 2; mt++) {
            uint32_t off = (uint32_t)((wm * 32 + mt * 16 + (lane & 15)) * 128
                                      + kk * 32 + ((lane >> 4) << 4));
            uint32_t so = swz(off);
            ldm4(sAh + so, ah[mt]);
            ldm4(sAl + so, al[mt]);
        }
        uint32_t bh[4][4], bl[4][4];
#pragma unroll
        for (int ng = 0; ng < 4; ng++) {
            int r = lane & 7, part = lane >> 3;
            int n = wn * 64 + ng * 16 + r + ((part >> 1) << 3);
            uint32_t off = (uint32_t)(n * 128 + kk * 32 + ((part & 1) << 4));
            uint32_t so = swz(off);
            ldm4(sBh + so, bh[ng]);
            ldm4(sBl + so, bl[ng]);
        }
#pragma unroll
        for (int mt = 0; mt < 2; mt++)
#pragma unroll
            for (int ng = 0; ng < 4; ng++)
#pragma unroll
                for (int h = 0; h < 2; h++) {
                    int nt = ng * 2 + h;
                    mma16816(acc[mt][nt], ah[mt], bh[ng][h * 2], bh[ng][h * 2 + 1]);
                    mma16816(acc[mt][nt], ah[mt], bl[ng][h * 2], bl[ng][h * 2 + 1]);
                    mma16816(acc[mt][nt], al[mt], bh[ng][h * 2], bh[ng][h * 2 + 1]);
                }
    }
}

#define STAGE_BYTES 65536
#define SMEM_BYTES (2 * STAGE_BYTES + 1024)

__global__ __launch_bounds__(256, 1) void gemm_mma(BatchArgs args) {
    extern __shared__ char smem_raw[];
    uint32_t sb = smem_u32(smem_raw);
    uint32_t al1k = (sb + 1023u) & ~1023u;
    char* st0 = smem_raw + (al1k - sb);
    uint32_t sb0 = al1k;

    int t = threadIdx.x;
    int lane = t & 31;
    int warp = t >> 5;
    int wm = warp >> 1, wn = warp & 1;
    int bid = blockIdx.x;

    int di = 0;
#pragma unroll
    for (int i = 1; i < 4; i++)
        if (i < args.nd && bid >= args.d[i].tile_base) di = i;
    const GemmDesc& g = args.d[di];

    int tile = bid - g.tile_base;
    int bm = tile / g.ntiles;
    int bn = tile - bm * g.ntiles;
    int m0 = bm << 7, n0 = bn << 7;
    int amode = (g.nch == 0 && g.transa) ? 1 : 0;

    float acc[2][8][4];
#pragma unroll
    for (int i = 0; i < 2; i++)
#pragma unroll
        for (int j = 0; j < 8; j++)
#pragma unroll
            for (int k = 0; k < 4; k++) acc[i][j][k] = 0.0f;

    int NC = g.K >> 6;

    float4 stA[8], stB[8];
    ldg_chunk(stA, stB, g, m0, n0, 0, t);
    sts_chunk(st0, stA, stB, t, amode);
    __syncthreads();

#pragma unroll 1
    for (int ci = 0; ci < NC; ci++) {
        if (ci + 1 < NC)
            ldg_chunk(stA, stB, g, m0, n0, (ci + 1) << 6, t);   // LDG only
        uint32_t s = sb0 + (ci & 1) * STAGE_BYTES;
        compute_chunk(s, s + 16384, s + 32768, s + 49152, wm, wn, lane, acc);
        if (ci + 1 < NC)
            sts_chunk(st0 + ((ci + 1) & 1) * STAGE_BYTES, stA, stB, t, amode);
        __syncthreads();
    }

    // Epilogue: acc[mt][nt] rows r0 = m0+wm*32+mt*16+(lane>>2), r1 = r0+8;
    //           cols c = n0+wn*64+nt*8+(lane&3)*2
    int ldc = g.ldc;
#pragma unroll
    for (int mt = 0; mt < 2; mt++) {
        int r0 = m0 + wm * 32 + mt * 16 + (lane >> 2);
        int r1 = r0 + 8;
        float s0 = 1.0f, s1 = 1.0f;
        if (g.epi == 0 && g.crow) {
            s0 = g.crow[(size_t)r0 * g.crs];
            s1 = g.crow[(size_t)r1 * g.crs];
        }
        float* C0 = g.C + (size_t)r0 * ldc;
        float* C1 = g.C + (size_t)r1 * ldc;
        const float* S0 = nullptr;
        const float* S1 = nullptr;
        if (g.epi == 1) {
            S0 = g.S + (size_t)r0 * g.lds;
            S1 = g.S + (size_t)r1 * g.lds;
        }
#pragma unroll
        for (int nt = 0; nt < 8; nt++) {
            int c = n0 + wn * 64 + nt * 8 + ((lane & 3) << 1);
            float d0 = acc[mt][nt][0], d1 = acc[mt][nt][1];
            float d2 = acc[mt][nt][2], d3 = acc[mt][nt][3];
            if (g.epi == 0) {
                *(float2*)(C0 + c) = make_float2(d0 * s0, d1 * s0);
                *(float2*)(C1 + c) = make_float2(d2 * s1, d3 * s1);
            } else if (g.epi == 1) {
                float2 sv0 = *(const float2*)(S0 + c);
                float2 sv1 = *(const float2*)(S1 + c);
                *(float2*)(C0 + c) = make_float2(2.f * d0 - sv0.x, 2.f * d1 - sv0.y);
                *(float2*)(C1 + c) = make_float2(2.f * d2 - sv1.x, 2.f * d3 - sv1.y);
            } else {
                *(float2*)(C0 + c) = make_float2(fmaxf(d0, 0.f), fmaxf(d1, 0.f));
                *(float2*)(C1 + c) = make_float2(fmaxf(d2, 0.f), fmaxf(d3, 0.f));
            }
        }
    }
}

// ---------------------------------------------------------------------------
// Prep kernels
// ---------------------------------------------------------------------------
__global__ void pack_kernel(float* __restrict__ dst, const float* __restrict__ w, int nk) {
    int idx = blockIdx.x * 256 + threadIdx.x;
    if (idx < 16384) {
        for (int c = 0; c < nk; c++) dst[c * 16384 + idx] = w[idx * nk + c];
    }
}
__global__ void copy_kernel(float* __restrict__ dst, const float* __restrict__ src, int rows) {
    int idx = blockIdx.x * 256 + threadIdx.x;
    int r = idx >> 5, q = (idx & 31) << 2;
    if (r < rows)
        *(float4*)(dst + (size_t)r * 256 + q) = *(const float4*)(src + (size_t)r * 128 + q);
}
// dst[r][:] = src[r][:] * diag[r] (diag read from full matrix diagonal, stride ds)
__global__ void scale_copy_kernel(float* __restrict__ dst, const float* __restrict__ src,
                                  const float* __restrict__ diag, int ds, int rows) {
    int idx = blockIdx.x * 256 + threadIdx.x;
    int r = idx >> 5, q = (idx & 31) << 2;
    if (r < rows) {
        float s = diag[(size_t)r * ds];
        float4 v = *(const float4*)(src + (size_t)r * 128 + q);
        v.x *= s; v.y *= s; v.z *= s; v.w *= s;
        *(float4*)(dst + (size_t)r * 128 + q) = v;
    }
}

// ---------------------------------------------------------------------------
// Host launcher
// ---------------------------------------------------------------------------
static GemmDesc mk(const float* A, int lda, int ta,
                   const float* B, int ldb,
                   float* C, int ldc,
                   const float* cr, int crs,
                   const float* S, int lds,
                   int K, int ntiles, int base, int epi) {
    GemmDesc g{};
    g.A = A; g.lda = lda; g.transa = ta;
    g.B = B; g.ldb = ldb;
    g.C = C; g.ldc = ldc;
    g.crow = cr; g.crs = crs;
    g.S = S; g.lds = lds;
    g.K = K; g.ntiles = ntiles; g.tile_base = base; g.epi = epi; g.nch = 0;
    return g;
}

extern "C" void kernel_launch(void* const* d_in, const int* in_sizes, int n_in,
                              void* d_out, int out_size) {
    const float* x0  = (const float*)d_in[0];
    const float* x1  = (const float*)d_in[1];
    const float* x2  = (const float*)d_in[2];
    const float* b1  = (const float*)d_in[3];
    const float* b2  = (const float*)d_in[4];
    const float* l0  = (const float*)d_in[5];
    const float* l1l = (const float*)d_in[6];
    const float* l1u = (const float*)d_in[7];
    const float* l2  = (const float*)d_in[8];
    const float* d1  = (const float*)d_in[9];
    const float* d3  = (const float*)d_in[10];
    const float* d5  = (const float*)d_in[11];
    const float* w0  = (const float*)d_in[12];
    const float* w1  = (const float*)d_in[13];
    const float* w2  = (const float*)d_in[14];
    float* out = (float*)d_out;
    (void)in_sizes; (void)n_in; (void)out_size;

    float *X0cat, *T10, *T20, *X1cat, *T1l, *T2l, *T1u, *T2u, *X2cat, *T12, *T22;
    float *W0, *W1, *W2, *x1s, *x2s;
    cudaGetSymbolAddress((void**)&X0cat, g_X0cat);
    cudaGetSymbolAddress((void**)&T10,   g_T10);
    cudaGetSymbolAddress((void**)&T20,   g_T20);
    cudaGetSymbolAddress((void**)&X1cat, g_X1cat);
    cudaGetSymbolAddress((void**)&T1l,   g_T1l);
    cudaGetSymbolAddress((void**)&T2l,   g_T2l);
    cudaGetSymbolAddress((void**)&T1u,   g_T1u);
    cudaGetSymbolAddress((void**)&T2u,   g_T2u);
    cudaGetSymbolAddress((void**)&X2cat, g_X2cat);
    cudaGetSymbolAddress((void**)&T12,   g_T12);
    cudaGetSymbolAddress((void**)&T22,   g_T22);
    cudaGetSymbolAddress((void**)&W0,    g_W0);
    cudaGetSymbolAddress((void**)&W1,    g_W1);
    cudaGetSymbolAddress((void**)&W2,    g_W2);
    cudaGetSymbolAddress((void**)&x1s,   g_x1s);
    cudaGetSymbolAddress((void**)&x2s,   g_x2s);

    cudaFuncSetAttribute(gemm_mma, cudaFuncAttributeMaxDynamicSharedMemorySize, SMEM_BYTES);

    // Prep
    pack_kernel<<<64, 256>>>(W0, w0, 6);
    pack_kernel<<<64, 256>>>(W1, w1, 8);
    pack_kernel<<<64, 256>>>(W2, w2, 6);
    copy_kernel<<<CN0 * 32 / 256, 256>>>(X0cat,       x0, CN0);
    copy_kernel<<<CN1 * 32 / 256, 256>>>(X1cat,       x1, CN1);
    copy_kernel<<<CN2 * 32 / 256, 256>>>(X2cat + 128, x2, CN2);
    scale_copy_kernel<<<CN1 * 32 / 256, 256>>>(x1s, x1, d5, CN1 + 1, CN1);
    scale_copy_kernel<<<CN2 * 32 / 256, 256>>>(x2s, x2, d3, CN2 + 1, CN2);

    // Wave 1: projections — 112 CTAs
    BatchArgs ba; ba.nd = 3;
    ba.d[0] = mk(b1, CN1, 0, x1, 128, X0cat + 128, 256,
                 d1, CN0 + 1, nullptr, 0, CN1, 1, 0, 0);
    ba.d[1] = mk(b2, CN2, 0, x2s, 128, X1cat + 128, 256,
                 nullptr, 0, nullptr, 0, CN2, 1, 16, 0);
    ba.d[2] = mk(b2, CN2, 1, x1s, 128, X2cat, 256,
                 nullptr, 0, nullptr, 0, CN1, 1, 80, 0);
    gemm_mma<<<112, 256, SMEM_BYTES>>>(ba);

    // Wave 2: T1 = L @ X — 288 CTAs
    BatchArgs bb; bb.nd = 4;
    bb.d[0] = mk(l0,  CN0, 0, X0cat, 256, T10, 256,
                 nullptr, 0, nullptr, 0, CN0, 2, 0, 0);
    bb.d[1] = mk(l1l, CN1, 0, x1,    128, T1l, 128,
                 nullptr, 0, nullptr, 0, CN1, 1, 32, 0);
    bb.d[2] = mk(l1u, CN1, 0, X1cat, 256, T1u, 256,
                 nullptr, 0, nullptr, 0, CN1, 2, 96, 0);
    bb.d[3] = mk(l2,  CN2, 0, X2cat, 256, T12, 256,
                 nullptr, 0, nullptr, 0, CN2, 2, 224, 0);
    gemm_mma<<<288, 256, SMEM_BYTES>>>(bb);

    // Wave 3: T2 = 2 L T1 - X — 288 CTAs
    BatchArgs bc; bc.nd = 4;
    bc.d[0] = mk(l0,  CN0, 0, T10, 256, T20, 256,
                 nullptr, 0, X0cat, 256, CN0, 2, 0, 1);
    bc.d[1] = mk(l1l, CN1, 0, T1l, 128, T2l, 128,
                 nullptr, 0, x1, 128, CN1, 1, 32, 1);
    bc.d[2] = mk(l1u, CN1, 0, T1u, 256, T2u, 256,
                 nullptr, 0, X1cat, 256, CN1, 2, 96, 1);
    bc.d[3] = mk(l2,  CN2, 0, T12, 256, T22, 256,
                 nullptr, 0, X2cat, 256, CN2, 2, 224, 1);
    gemm_mma<<<288, 256, SMEM_BYTES>>>(bc);

    // Wave 4: combine + relu — 112 CTAs (multi-channel K)
    BatchArgs bd; bd.nd = 3;
    {
        GemmDesc g = mk(nullptr, 0, 0, W0, 128, out, 128,
                        nullptr, 0, nullptr, 0, 6 * 128, 1, 0, 2);
        g.nch = 6;
        const float* ch[6] = {X0cat, T10, T20, X0cat + 128, T10 + 128, T20 + 128};
        for (int c = 0; c < 6; c++) { g.Achan[c] = ch[c]; g.Alda[c] = 256; }
        bd.d[0] = g;
    }
    {
        GemmDesc g = mk(nullptr, 0, 0, W1, 128, out + (size_t)CN0 * 128, 128,
                        nullptr, 0, nullptr, 0, 8 * 128, 1, 16, 2);
        g.nch = 8;
        const float* ch[8] = {X1cat, T1l, T2l, T1u, T2u,
                              X1cat + 128, T1u + 128, T2u + 128};
        int ld[8] = {256, 128, 128, 256, 256, 256, 256, 256};
        for (int c = 0; c < 8; c++) { g.Achan[c] = ch[c]; g.Alda[c] = ld[c]; }
        bd.d[1] = g;
    }
    {
        GemmDesc g = mk(nullptr, 0, 0, W2, 128, out + (size_t)(CN0 + CN1) * 128, 128,
                        nullptr, 0, nullptr, 0, 6 * 128, 1, 80, 2);
        g.nch = 6;
        const float* ch[6] = {X2cat, T12, T22, X2cat + 128, T12 + 128, T22 + 128};
        for (int c = 0; c < 6; c++) { g.Achan[c] = ch[c]; g.Alda[c] = 256; }
        bd.d[2] = g;
    }
    gemm_mma<<<112, 256, SMEM_BYTES>>>(bd);
}